// round 6
// baseline (speedup 1.0000x reference)
#include <cuda_runtime.h>
#include <cuda_bf16.h>
#include <math.h>

// total = sum_i [ 0.5*w^2 - 0.5*((w-mu)/sig)^2 - log(sig) ]   (weights)
//       + sum_j [ 0.5*((y-mup)/sp)^2 ]                         (likelihood, negated)
//       + B * (log(sp) + HALF_LOG_2PI)                         (closed-form constant)
//
// Per-warp work-stealing over 128-float4 chunks; per-lane per-chunk partials are
// converted to int64 fixed-point so the final sum is order-independent
// (bit-deterministic across graph replays despite dynamic scheduling).

#define HALF_LOG_2PI 0.9189385332046727

static constexpr int    BLOCKS     = 296;        // 148 SMs x 2 CTAs, single wave
static constexpr int    THREADS    = 256;
static constexpr int    CHUNK_LOG2 = 7;          // 128 float4 indexes per warp-chunk
static constexpr double FXSCALE    = 4194304.0;  // 2^22 fixed-point scale

__device__ long long    g_sum    = 0;  // fixed-point total (order-independent)
__device__ unsigned int g_ticket = 0;  // chunk grabber
__device__ unsigned int g_done   = 0;  // warp completion counter

__device__ __forceinline__ float frcp_fast(float x) {
    float r;
    asm("rcp.approx.ftz.f32 %0, %1;" : "=f"(r) : "f"(x));
    return r;
}

// streaming LDG.128 with L2 256B prefetch hint
__device__ __forceinline__ float4 ldcs_pf(const float4* p) {
    float4 v;
    asm volatile("ld.global.cs.L2::256B.v4.f32 {%0,%1,%2,%3}, [%4];"
                 : "=f"(v.x), "=f"(v.y), "=f"(v.z), "=f"(v.w) : "l"(p));
    return v;
}

__device__ __forceinline__ float term5(float w, float mu, float sg,
                                       float mp, float yt, float inv_sp) {
    float z = (w - mu) * frcp_fast(sg);
    float u = (yt - mp) * inv_sp;
    return 0.5f * w * w - 0.5f * z * z - __logf(sg) + 0.5f * u * u;
}

__device__ __forceinline__ float quad(const float4& a, const float4& b,
                                      const float4& c, const float4& d,
                                      const float4& e, float inv_sp) {
    return term5(a.x, b.x, c.x, d.x, e.x, inv_sp)
         + term5(a.y, b.y, c.y, d.y, e.y, inv_sp)
         + term5(a.z, b.z, c.z, d.z, e.z, inv_sp)
         + term5(a.w, b.w, c.w, d.w, e.w, inv_sp);
}

__global__ __launch_bounds__(THREADS, 2)
void fused_loss_kernel(const float4* __restrict__ w,
                       const float4* __restrict__ mu,
                       const float4* __restrict__ sg,
                       const float4* __restrict__ mp,
                       const float4* __restrict__ yt,
                       const float*  __restrict__ sp_ptr,
                       float* __restrict__ out,
                       int n4, int n_batch) {
    const float inv_sp = frcp_fast(*sp_ptr);
    const int   lane    = threadIdx.x & 31;
    const int   nchunks = n4 >> CHUNK_LOG2;

    long long accfx = 0;

    // prologue: grab first chunk
    unsigned c = 0;
    if (lane == 0) c = atomicAdd(&g_ticket, 1u);
    c = __shfl_sync(0xFFFFFFFFu, c, 0);

    while (c < (unsigned)nchunks) {
        // prefetch next ticket NOW; its 318-cyc latency hides under this chunk
        unsigned cn = 0;
        if (lane == 0) cn = atomicAdd(&g_ticket, 1u);

        int i0 = ((int)c << CHUNK_LOG2) + lane;   // chunk base + lane
        int i1 = i0 + 32, i2 = i0 + 64, i3 = i0 + 96;

        float4 a0 = ldcs_pf(&w[i0]),  b0 = ldcs_pf(&mu[i0]),  c0 = ldcs_pf(&sg[i0]),
               d0 = ldcs_pf(&mp[i0]), e0 = ldcs_pf(&yt[i0]);
        float4 a1 = ldcs_pf(&w[i1]),  b1 = ldcs_pf(&mu[i1]),  c1 = ldcs_pf(&sg[i1]),
               d1 = ldcs_pf(&mp[i1]), e1 = ldcs_pf(&yt[i1]);
        float4 a2 = ldcs_pf(&w[i2]),  b2 = ldcs_pf(&mu[i2]),  c2 = ldcs_pf(&sg[i2]),
               d2 = ldcs_pf(&mp[i2]), e2 = ldcs_pf(&yt[i2]);
        float4 a3 = ldcs_pf(&w[i3]),  b3 = ldcs_pf(&mu[i3]),  c3 = ldcs_pf(&sg[i3]),
               d3 = ldcs_pf(&mp[i3]), e3 = ldcs_pf(&yt[i3]);

        // fixed evaluation order within a chunk -> deterministic chunk partial
        float s = (quad(a0, b0, c0, d0, e0, inv_sp) + quad(a1, b1, c1, d1, e1, inv_sp))
                + (quad(a2, b2, c2, d2, e2, inv_sp) + quad(a3, b3, c3, d3, e3, inv_sp));

        // integer accumulation: order-independent across chunk assignments
        accfx += __double2ll_rn((double)s * FXSCALE);

        c = __shfl_sync(0xFFFFFFFFu, cn, 0);
    }

    // leftover indexes (none when n4 % 128 == 0) -- static, deterministic
    for (int i = (nchunks << CHUNK_LOG2) + blockIdx.x * blockDim.x + threadIdx.x;
         i < n4; i += gridDim.x * blockDim.x) {
        float4 a = ldcs_pf(&w[i]), b = ldcs_pf(&mu[i]), c2_ = ldcs_pf(&sg[i]),
               d = ldcs_pf(&mp[i]), e = ldcs_pf(&yt[i]);
        float s = quad(a, b, c2_, d, e, inv_sp);
        accfx += __double2ll_rn((double)s * FXSCALE);
    }

    // warp reduce (int64, order irrelevant)
    #pragma unroll
    for (int off = 16; off > 0; off >>= 1)
        accfx += __shfl_xor_sync(0xFFFFFFFFu, accfx, off);

    if (lane == 0) {
        atomicAdd((unsigned long long*)&g_sum, (unsigned long long)accfx);
        __threadfence();
        unsigned nwarps = gridDim.x * (blockDim.x >> 5);
        unsigned t = atomicAdd(&g_done, 1u);
        if (t == nwarps - 1) {
            long long tot = (long long)atomicAdd((unsigned long long*)&g_sum, 0ull);
            double total = (double)tot / FXSCALE;
            double sp = (double)(*sp_ptr);
            double cc = (double)n_batch * (log(sp) + HALF_LOG_2PI);
            out[0] = (float)(total + cc);
            g_sum    = 0;   // reset for next graph replay
            g_done   = 0;
            g_ticket = 0;
        }
    }
}

extern "C" void kernel_launch(void* const* d_in, const int* in_sizes, int n_in,
                              void* d_out, int out_size) {
    // metadata order: noisy_weights, mu_weights, sigma_weights,
    //                 mu_prediction, sigma_prediction (scalar), y_true
    const float4* w  = (const float4*)d_in[0];
    const float4* mu = (const float4*)d_in[1];
    const float4* sg = (const float4*)d_in[2];
    const float4* mp = (const float4*)d_in[3];
    const float*  sp = (const float*) d_in[4];
    const float4* yt = (const float4*)d_in[5];

    int n  = in_sizes[0];      // 2^24, divisible by 4
    int n4 = n >> 2;

    fused_loss_kernel<<<BLOCKS, THREADS>>>(w, mu, sg, mp, yt, sp,
                                           (float*)d_out, n4, in_sizes[5]);
}

// round 7
// speedup vs baseline: 1.0821x; 1.0821x over previous
#include <cuda_runtime.h>
#include <cuda_bf16.h>
#include <math.h>

// total = sum_i [ 0.5*(w^2 - ((w-mu)/sig)^2) - log(sig) ]   (weights)
//       + sum_j [ 0.5*((y-mup)/sp)^2 ]                       (likelihood, negated)
//       + B * (log(sp) + HALF_LOG_2PI)                       (closed-form constant)
// Grouped log: sum of 4 log(sig) = ln2 * log2(prod of 4 sig), sig in [0.5,1.5).

#define HALF_LOG_2PI 0.9189385332046727
#define LN2F 0.6931471805599453f

static constexpr int    BLOCKS  = 296;   // 148 SMs x 2 resident blocks -> single wave
static constexpr int    THREADS = 256;
static constexpr double FXSCALE = 4194304.0;   // 2^22 fixed-point scale

__device__ long long    g_sum   = 0;   // fixed-point accumulator (order-independent)
__device__ unsigned int g_count = 0;   // arrival ticket; reset each launch

__device__ __forceinline__ float frcp_fast(float x) {
    float r;
    asm("rcp.approx.ftz.f32 %0, %1;" : "=f"(r) : "f"(x));
    return r;
}

// streaming LDG.128 with L2 256B prefetch hint
__device__ __forceinline__ float4 ldcs_pf(const float4* p) {
    float4 v;
    asm volatile("ld.global.cs.L2::256B.v4.f32 {%0,%1,%2,%3}, [%4];"
                 : "=f"(v.x), "=f"(v.y), "=f"(v.z), "=f"(v.w) : "l"(p));
    return v;
}

__device__ __forceinline__ float quad(const float4& a, const float4& b,
                                      const float4& c, const float4& d,
                                      const float4& e, float inv_sp) {
    // z terms (variational), one rcp each
    float zx = (a.x - b.x) * frcp_fast(c.x);
    float zy = (a.y - b.y) * frcp_fast(c.y);
    float zz = (a.z - b.z) * frcp_fast(c.z);
    float zw = (a.w - b.w) * frcp_fast(c.w);
    // u terms (likelihood)
    float ux = (e.x - d.x) * inv_sp;
    float uy = (e.y - d.y) * inv_sp;
    float uz = (e.z - d.z) * inv_sp;
    float uw = (e.w - d.w) * inv_sp;

    float sq = (a.x * a.x - zx * zx) + (a.y * a.y - zy * zy)
             + (a.z * a.z - zz * zz) + (a.w * a.w - zw * zw)
             + (ux * ux + uy * uy) + (uz * uz + uw * uw);

    // grouped log: one MUFU.LG2 for four sigmas
    float prod = (c.x * c.y) * (c.z * c.w);
    return 0.5f * sq - LN2F * __log2f(prod);
}

__global__ __launch_bounds__(THREADS, 2)
void fused_loss_kernel(const float4* __restrict__ w,
                       const float4* __restrict__ mu,
                       const float4* __restrict__ sg,
                       const float4* __restrict__ mp,
                       const float4* __restrict__ yt,
                       const float*  __restrict__ sp_ptr,
                       float* __restrict__ out,
                       int n4, int n_batch) {
    const float inv_sp = frcp_fast(*sp_ptr);
    const int stride  = gridDim.x * blockDim.x;
    const int stride4 = stride * 4;

    float acc0 = 0.0f, acc1 = 0.0f, acc2 = 0.0f, acc3 = 0.0f;
    int i = blockIdx.x * blockDim.x + threadIdx.x;

    // main loop: 4x unrolled, all 20 LDG.128 front-batched
    for (; i + 3 * stride < n4; i += stride4) {
        int i1 = i + stride, i2 = i + 2 * stride, i3 = i + 3 * stride;
        float4 a0 = ldcs_pf(&w[i]),  b0 = ldcs_pf(&mu[i]),  c0 = ldcs_pf(&sg[i]),
               d0 = ldcs_pf(&mp[i]), e0 = ldcs_pf(&yt[i]);
        float4 a1 = ldcs_pf(&w[i1]), b1 = ldcs_pf(&mu[i1]), c1 = ldcs_pf(&sg[i1]),
               d1 = ldcs_pf(&mp[i1]), e1 = ldcs_pf(&yt[i1]);
        float4 a2 = ldcs_pf(&w[i2]), b2 = ldcs_pf(&mu[i2]), c2 = ldcs_pf(&sg[i2]),
               d2 = ldcs_pf(&mp[i2]), e2 = ldcs_pf(&yt[i2]);
        float4 a3 = ldcs_pf(&w[i3]), b3 = ldcs_pf(&mu[i3]), c3 = ldcs_pf(&sg[i3]),
               d3 = ldcs_pf(&mp[i3]), e3 = ldcs_pf(&yt[i3]);
        acc0 += quad(a0, b0, c0, d0, e0, inv_sp);
        acc1 += quad(a1, b1, c1, d1, e1, inv_sp);
        acc2 += quad(a2, b2, c2, d2, e2, inv_sp);
        acc3 += quad(a3, b3, c3, d3, e3, inv_sp);
    }
    for (; i < n4; i += stride) {
        float4 a = ldcs_pf(&w[i]), b = ldcs_pf(&mu[i]), c = ldcs_pf(&sg[i]),
               d = ldcs_pf(&mp[i]), e = ldcs_pf(&yt[i]);
        acc0 += quad(a, b, c, d, e, inv_sp);
    }

    float acc = (acc0 + acc1) + (acc2 + acc3);

    // warp reduce
    #pragma unroll
    for (int off = 16; off > 0; off >>= 1)
        acc += __shfl_xor_sync(0xFFFFFFFFu, acc, off);

    __shared__ double s_warp[THREADS / 32];
    int lane = threadIdx.x & 31;
    int wid  = threadIdx.x >> 5;
    if (lane == 0) s_warp[wid] = (double)acc;
    __syncthreads();

    if (threadIdx.x == 0) {
        double bsum = 0.0;
        #pragma unroll
        for (int k = 0; k < THREADS / 32; k++) bsum += s_warp[k];

        // fixed-point contribution: integer adds are order-independent -> deterministic
        long long fx = __double2ll_rn(bsum * FXSCALE);
        atomicAdd((unsigned long long*)&g_sum, (unsigned long long)fx);
        __threadfence();
        unsigned int ticket = atomicAdd(&g_count, 1u);
        if (ticket == (unsigned int)(gridDim.x - 1)) {
            long long total_fx =
                (long long)atomicAdd((unsigned long long*)&g_sum, 0ull);
            double total = (double)total_fx / FXSCALE;
            double sp = (double)(*sp_ptr);
            double c  = (double)n_batch * (log(sp) + HALF_LOG_2PI);
            out[0] = (float)(total + c);
            g_sum   = 0;   // reset for next graph replay
            g_count = 0;
        }
    }
}

extern "C" void kernel_launch(void* const* d_in, const int* in_sizes, int n_in,
                              void* d_out, int out_size) {
    // metadata order: noisy_weights, mu_weights, sigma_weights,
    //                 mu_prediction, sigma_prediction (scalar), y_true
    const float4* w  = (const float4*)d_in[0];
    const float4* mu = (const float4*)d_in[1];
    const float4* sg = (const float4*)d_in[2];
    const float4* mp = (const float4*)d_in[3];
    const float*  sp = (const float*) d_in[4];
    const float4* yt = (const float4*)d_in[5];

    int n  = in_sizes[0];      // 2^24, divisible by 4
    int n4 = n >> 2;

    fused_loss_kernel<<<BLOCKS, THREADS>>>(w, mu, sg, mp, yt, sp,
                                           (float*)d_out, n4, in_sizes[5]);
}

// round 8
// speedup vs baseline: 1.1090x; 1.0249x over previous
#include <cuda_runtime.h>
#include <cuda_bf16.h>
#include <math.h>

// total = sum_i [ 0.5*(w^2 - ((w-mu)/sig)^2) - log(sig) ]   (weights)
//       + sum_j [ 0.5*((y-mup)/sp)^2 ]                       (likelihood, negated)
//       + B * (log(sp) + HALF_LOG_2PI)                       (closed-form constant)
//
// Hybrid schedule: first S indexes (84%) via fully-pipelined static grid-stride;
// last 16% via warp-level chunk stealing to absorb between-SM speed spread.
// All partials converted to int64 fixed-point -> order-independent, deterministic.

#define HALF_LOG_2PI 0.9189385332046727
#define LN2F 0.6931471805599453f

static constexpr int    BLOCKS  = 296;   // 148 SMs x 2 resident blocks, single wave
static constexpr int    THREADS = 256;
static constexpr double FXSCALE = 4194304.0;   // 2^22

__device__ long long    g_sum    = 0;
__device__ unsigned int g_ticket = 0;
__device__ unsigned int g_done   = 0;

__device__ __forceinline__ float frcp_fast(float x) {
    float r;
    asm("rcp.approx.ftz.f32 %0, %1;" : "=f"(r) : "f"(x));
    return r;
}

__device__ __forceinline__ float4 ldcs_pf(const float4* p) {
    float4 v;
    asm volatile("ld.global.cs.L2::256B.v4.f32 {%0,%1,%2,%3}, [%4];"
                 : "=f"(v.x), "=f"(v.y), "=f"(v.z), "=f"(v.w) : "l"(p));
    return v;
}

__device__ __forceinline__ float quad(const float4& a, const float4& b,
                                      const float4& c, const float4& d,
                                      const float4& e, float inv_sp) {
    float zx = (a.x - b.x) * frcp_fast(c.x);
    float zy = (a.y - b.y) * frcp_fast(c.y);
    float zz = (a.z - b.z) * frcp_fast(c.z);
    float zw = (a.w - b.w) * frcp_fast(c.w);
    float ux = (e.x - d.x) * inv_sp;
    float uy = (e.y - d.y) * inv_sp;
    float uz = (e.z - d.z) * inv_sp;
    float uw = (e.w - d.w) * inv_sp;

    float sq = (a.x * a.x - zx * zx) + (a.y * a.y - zy * zy)
             + (a.z * a.z - zz * zz) + (a.w * a.w - zw * zw)
             + (ux * ux + uy * uy) + (uz * uz + uw * uw);

    float prod = (c.x * c.y) * (c.z * c.w);   // grouped log: 1 MUFU per 4 sigmas
    return 0.5f * sq - LN2F * __log2f(prod);
}

__global__ __launch_bounds__(THREADS, 2)
void fused_loss_kernel(const float4* __restrict__ w,
                       const float4* __restrict__ mu,
                       const float4* __restrict__ sg,
                       const float4* __restrict__ mp,
                       const float4* __restrict__ yt,
                       const float*  __restrict__ sp_ptr,
                       float* __restrict__ out,
                       int S, int nchunks, int n_batch) {
    const float inv_sp = frcp_fast(*sp_ptr);
    const int stride  = gridDim.x * blockDim.x;
    const int stride4 = stride * 4;
    const int lane    = threadIdx.x & 31;

    // ---- static region [0, S): fully pipelined, 4x unroll, 20 LDG front-batched
    float acc0 = 0.0f, acc1 = 0.0f, acc2 = 0.0f, acc3 = 0.0f;
    int i = blockIdx.x * blockDim.x + threadIdx.x;
    for (; i + 3 * stride < S; i += stride4) {
        int i1 = i + stride, i2 = i + 2 * stride, i3 = i + 3 * stride;
        float4 a0 = ldcs_pf(&w[i]),  b0 = ldcs_pf(&mu[i]),  c0 = ldcs_pf(&sg[i]),
               d0 = ldcs_pf(&mp[i]), e0 = ldcs_pf(&yt[i]);
        float4 a1 = ldcs_pf(&w[i1]), b1 = ldcs_pf(&mu[i1]), c1 = ldcs_pf(&sg[i1]),
               d1 = ldcs_pf(&mp[i1]), e1 = ldcs_pf(&yt[i1]);
        float4 a2 = ldcs_pf(&w[i2]), b2 = ldcs_pf(&mu[i2]), c2 = ldcs_pf(&sg[i2]),
               d2 = ldcs_pf(&mp[i2]), e2 = ldcs_pf(&yt[i2]);
        float4 a3 = ldcs_pf(&w[i3]), b3 = ldcs_pf(&mu[i3]), c3 = ldcs_pf(&sg[i3]),
               d3 = ldcs_pf(&mp[i3]), e3 = ldcs_pf(&yt[i3]);
        acc0 += quad(a0, b0, c0, d0, e0, inv_sp);
        acc1 += quad(a1, b1, c1, d1, e1, inv_sp);
        acc2 += quad(a2, b2, c2, d2, e2, inv_sp);
        acc3 += quad(a3, b3, c3, d3, e3, inv_sp);
    }
    for (; i < S; i += stride) {
        float4 a = ldcs_pf(&w[i]), b = ldcs_pf(&mu[i]), c = ldcs_pf(&sg[i]),
               d = ldcs_pf(&mp[i]), e = ldcs_pf(&yt[i]);
        acc0 += quad(a, b, c, d, e, inv_sp);
    }

    // static partial is schedule-independent -> convert once
    long long accfx =
        __double2ll_rn((double)((acc0 + acc1) + (acc2 + acc3)) * FXSCALE);

    // ---- dynamic tail [S, S + nchunks*128): warp-level chunk stealing
    unsigned c = 0;
    if (lane == 0) c = atomicAdd(&g_ticket, 1u);
    c = __shfl_sync(0xFFFFFFFFu, c, 0);
    while (c < (unsigned)nchunks) {
        unsigned cn = 0;
        if (lane == 0) cn = atomicAdd(&g_ticket, 1u);   // prefetch next ticket

        int j0 = S + ((int)c << 7) + lane;
        int j1 = j0 + 32, j2 = j0 + 64, j3 = j0 + 96;
        float4 a0 = ldcs_pf(&w[j0]),  b0 = ldcs_pf(&mu[j0]),  c0 = ldcs_pf(&sg[j0]),
               d0 = ldcs_pf(&mp[j0]), e0 = ldcs_pf(&yt[j0]);
        float4 a1 = ldcs_pf(&w[j1]),  b1 = ldcs_pf(&mu[j1]),  c1 = ldcs_pf(&sg[j1]),
               d1 = ldcs_pf(&mp[j1]), e1 = ldcs_pf(&yt[j1]);
        float4 a2 = ldcs_pf(&w[j2]),  b2 = ldcs_pf(&mu[j2]),  c2 = ldcs_pf(&sg[j2]),
               d2 = ldcs_pf(&mp[j2]), e2 = ldcs_pf(&yt[j2]);
        float4 a3 = ldcs_pf(&w[j3]),  b3 = ldcs_pf(&mu[j3]),  c3 = ldcs_pf(&sg[j3]),
               d3 = ldcs_pf(&mp[j3]), e3 = ldcs_pf(&yt[j3]);

        float s = (quad(a0, b0, c0, d0, e0, inv_sp) + quad(a1, b1, c1, d1, e1, inv_sp))
                + (quad(a2, b2, c2, d2, e2, inv_sp) + quad(a3, b3, c3, d3, e3, inv_sp));
        accfx += __double2ll_rn((double)s * FXSCALE);   // order-independent

        c = __shfl_sync(0xFFFFFFFFu, cn, 0);
    }

    // ---- warp reduce (int64) + global finalize
    #pragma unroll
    for (int off = 16; off > 0; off >>= 1)
        accfx += __shfl_xor_sync(0xFFFFFFFFu, accfx, off);

    if (lane == 0) {
        atomicAdd((unsigned long long*)&g_sum, (unsigned long long)accfx);
        __threadfence();
        unsigned nwarps = gridDim.x * (blockDim.x >> 5);
        unsigned t = atomicAdd(&g_done, 1u);
        if (t == nwarps - 1) {
            long long tot = (long long)atomicAdd((unsigned long long*)&g_sum, 0ull);
            double total = (double)tot / FXSCALE;
            double sp = (double)(*sp_ptr);
            double cc = (double)n_batch * (log(sp) + HALF_LOG_2PI);
            out[0] = (float)(total + cc);
            g_sum    = 0;   // reset for next graph replay
            g_done   = 0;
            g_ticket = 0;
        }
    }
}

extern "C" void kernel_launch(void* const* d_in, const int* in_sizes, int n_in,
                              void* d_out, int out_size) {
    // metadata order: noisy_weights, mu_weights, sigma_weights,
    //                 mu_prediction, sigma_prediction (scalar), y_true
    const float4* w  = (const float4*)d_in[0];
    const float4* mu = (const float4*)d_in[1];
    const float4* sg = (const float4*)d_in[2];
    const float4* mp = (const float4*)d_in[3];
    const float*  sp = (const float*) d_in[4];
    const float4* yt = (const float4*)d_in[5];

    int n  = in_sizes[0];      // 2^24, divisible by 4
    int n4 = n >> 2;

    // 84% static (chunk-aligned), 16% stolen in 128-float4 warp chunks
    int S       = (int)(((long long)n4 * 84 / 100) & ~127LL);
    int nchunks = (n4 - S) >> 7;
    // any残 leftover (n4 not multiple of 128) folded into static region
    S = n4 - (nchunks << 7);

    fused_loss_kernel<<<BLOCKS, THREADS>>>(w, mu, sg, mp, yt, sp,
                                           (float*)d_out, S, nchunks, in_sizes[5]);
}